// round 2
// baseline (speedup 1.0000x reference)
#include <cuda_runtime.h>
#include <math.h>

// BalancedAveragedHausdorffLoss via exact Euclidean Distance Transform.
// B=8, C=4, H=W=64 -> N=32 items, HW=4096 pixels each.
//
// For each item:
//   pmask = |pred-1| <= 0.3 + 1e-5
//   tmask = target != 0
//   term1 = sum_{p in pmask} min_{t in tmask} dist(p,t)
//   term2 = sum_{t in tmask} min_{p in pmask} dist(p,t)
//   val   = (nt>0 && np>0) ? (term1+term2) / (2*nt) : 0
// loss = mean over items.
//
// min-dist-to-mask over a grid == EDT of the mask. Computed exactly in
// integer arithmetic (squared distances), sqrtf applied once per summed pixel.

#define ITEMS 32
#define Wdim  64
#define HW    4096
#define GINF  127          // > 63; 127^2 = 16129 > max real d2 = 63^2+63^2 = 7938

// Per-(item,direction) partial results. Every slot is written unconditionally
// on every launch -> deterministic, no zero-init needed, graph-safe.
__device__ float g_terms[2 * ITEMS];   // [2*item + which]
__device__ int   g_counts[2 * ITEMS];  // [2*item] = n_t, [2*item+1] = n_p

// One block per (item, which). which==0: EDT of target mask, summed over pred
// pixels (term1). which==1: EDT of pred mask, summed over target pixels (term2).
__global__ __launch_bounds__(256)
void bahl_edt_kernel(const float* __restrict__ pred,
                     const float* __restrict__ target)
{
    __shared__ unsigned char srcm[HW];   // mask the EDT is computed FROM
    __shared__ unsigned char dstm[HW];   // mask the distances are summed OVER
    __shared__ int g2s[HW];              // phase-1 result, squared (row-major)
    __shared__ float sacc[8];
    __shared__ int   sct[8], scp[8];

    const int bi    = blockIdx.x;
    const int item  = bi >> 1;
    const int which = bi & 1;
    const int tid   = threadIdx.x;

    const float* pb = pred   + item * HW;
    const float* tb = target + item * HW;

    // --- Build masks + per-thread counts -------------------------------
    const float THR = 0.30001f;   // atol + rtol*|1.0| in float32
    int ct = 0, cp = 0;
    for (int i = tid; i < HW; i += 256) {
        float pv = pb[i];
        float tv = tb[i];
        unsigned char pm = (fabsf(pv - 1.0f) <= THR) ? 1 : 0;
        unsigned char tm = (tv != 0.0f) ? 1 : 0;
        ct += tm; cp += pm;
        if (which == 0) { srcm[i] = tm; dstm[i] = pm; }
        else            { srcm[i] = pm; dstm[i] = tm; }
    }
    __syncthreads();

    // --- Phase 1: per-column vertical distance (two scans), store g^2 ---
    if (tid < Wdim) {
        const int c = tid;
        int d = GINF;
        #pragma unroll 1
        for (int x = 0; x < Wdim; x++) {
            d = srcm[x * Wdim + c] ? 0 : min(d + 1, GINF);
            g2s[x * Wdim + c] = d;
        }
        d = GINF;
        #pragma unroll 1
        for (int x = Wdim - 1; x >= 0; x--) {
            d = srcm[x * Wdim + c] ? 0 : min(d + 1, GINF);
            int g = min(g2s[x * Wdim + c], d);
            g2s[x * Wdim + c] = g * g;
        }
    }
    __syncthreads();

    // --- Phase 2: per-pixel min over row of (dy^2 + g^2), then masked sum.
    // Each warp's 32 consecutive pixels lie in one row -> g2s reads broadcast.
    float acc = 0.0f;
    for (int pix = tid; pix < HW; pix += 256) {
        const int row = pix >> 6;
        const int y   = pix & 63;
        const int* __restrict__ grow = &g2s[row * Wdim];
        int dmin = 0x7fffffff;
        #pragma unroll
        for (int yp = 0; yp < Wdim; yp++) {
            int dy   = y - yp;
            int cand = dy * dy + grow[yp];
            dmin = min(dmin, cand);
        }
        if (dstm[pix]) acc += sqrtf((float)dmin);
    }

    // --- Block reduction ------------------------------------------------
    #pragma unroll
    for (int o = 16; o > 0; o >>= 1) {
        acc += __shfl_xor_sync(0xffffffffu, acc, o);
        ct  += __shfl_xor_sync(0xffffffffu, ct,  o);
        cp  += __shfl_xor_sync(0xffffffffu, cp,  o);
    }
    const int wid = tid >> 5, lid = tid & 31;
    if (lid == 0) { sacc[wid] = acc; sct[wid] = ct; scp[wid] = cp; }
    __syncthreads();
    if (tid == 0) {
        float a = 0.0f; int t = 0, p = 0;
        #pragma unroll
        for (int w = 0; w < 8; w++) { a += sacc[w]; t += sct[w]; p += scp[w]; }
        g_terms[bi] = a;
        if (which == 0) {
            g_counts[2 * item]     = t;   // n_t
            g_counts[2 * item + 1] = p;   // n_p
        }
    }
}

__global__ void bahl_finalize_kernel(float* __restrict__ out)
{
    const int i = threadIdx.x;   // 32 threads, one per item
    float v = 0.0f;
    if (i < ITEMS) {
        float t1 = g_terms[2 * i];
        float t2 = g_terms[2 * i + 1];
        int   nt = g_counts[2 * i];
        int   np = g_counts[2 * i + 1];
        v = (nt > 0 && np > 0) ? (t1 + t2) / (2.0f * (float)nt) : 0.0f;
    }
    #pragma unroll
    for (int o = 16; o > 0; o >>= 1)
        v += __shfl_xor_sync(0xffffffffu, v, o);
    if (i == 0) out[0] = v / (float)ITEMS;
}

extern "C" void kernel_launch(void* const* d_in, const int* in_sizes, int n_in,
                              void* d_out, int out_size)
{
    const float* pred   = (const float*)d_in[0];
    const float* target = (const float*)d_in[1];
    float* out = (float*)d_out;
    (void)in_sizes; (void)n_in; (void)out_size;

    bahl_edt_kernel<<<2 * ITEMS, 256>>>(pred, target);
    bahl_finalize_kernel<<<1, 32>>>(out);
}